// round 2
// baseline (speedup 1.0000x reference)
#include <cuda_runtime.h>
#include <math.h>

#define TT 2048
#define NN 64
#define EE 1024
#define AA 256

// Scratch (allocation-free rule: __device__ globals)
__device__ float g_dproj[NN * AA];      // [n][a]
__device__ float g_scores[TT * NN];     // [t][n]

// ---------------------------------------------------------------------------
// Kernel 1: d_proj[n][a] = sum_k dec_h[n][k] * W_d[a][k]
// grid = 64 (one per n), block = 256 (8 warps, warp per a, strided)
// ---------------------------------------------------------------------------
__global__ void dproj_kernel(const float* __restrict__ dec_h,
                             const float* __restrict__ W_d) {
    __shared__ float dh[EE];
    int n = blockIdx.x;
    for (int k = threadIdx.x; k < EE; k += blockDim.x) dh[k] = dec_h[n * EE + k];
    __syncthreads();
    int warp = threadIdx.x >> 5, lane = threadIdx.x & 31;
    const float4* dh4 = (const float4*)dh;
    for (int a = warp; a < AA; a += 8) {
        const float4* w4 = (const float4*)(W_d + (size_t)a * EE);
        float acc = 0.f;
        #pragma unroll 4
        for (int k = lane; k < EE / 4; k += 32) {
            float4 w = w4[k], d = dh4[k];
            acc += w.x * d.x + w.y * d.y + w.z * d.z + w.w * d.w;
        }
        #pragma unroll
        for (int off = 16; off; off >>= 1)
            acc += __shfl_xor_sync(0xffffffffu, acc, off);
        if (lane == 0) g_dproj[n * AA + a] = acc;
    }
}

// ---------------------------------------------------------------------------
// Kernel 2: fused scores.
//   C[rl][a] = sum_k enc[t][rl][k] * W_e[a][k]     (rl == n, block per t)
//   score[t][n] = sum_a tanh(C + dproj[n][a]) * v[a]
// Tile: BM=64 rows x BN=256 cols, BK=16. 256 threads, 8x8 register tile.
// Warp ty owns rows ty*8..ty*8+7 (all lanes same rows -> warp-reduce over a).
// ---------------------------------------------------------------------------
#define BK 16
__global__ __launch_bounds__(256, 2)
void score_kernel(const float* __restrict__ enc,
                  const float* __restrict__ W_e,
                  const float* __restrict__ v) {
    __shared__ float Xs[BK][64];    // [kk][row]
    __shared__ float Ws[BK][AA];    // [kk][col]

    int t = blockIdx.x;
    const float* X = enc + (size_t)t * NN * EE;   // 64 rows x 1024
    int tid = threadIdx.x;
    int ty = tid >> 5;        // warp id 0..7 -> row group
    int tx = tid & 31;        // lane -> col group

    float acc[8][8];
    #pragma unroll
    for (int i = 0; i < 8; i++)
        #pragma unroll
        for (int j = 0; j < 8; j++) acc[i][j] = 0.f;

    int xrow = tid >> 2;      // 0..63
    int xq   = tid & 3;       // 0..3 -> k offset xq*4

    for (int k0 = 0; k0 < EE; k0 += BK) {
        // load X tile: 64 rows x 16 k  (one float4 per thread)
        {
            float4 rv = *(const float4*)(X + (size_t)xrow * EE + k0 + xq * 4);
            Xs[xq * 4 + 0][xrow] = rv.x;
            Xs[xq * 4 + 1][xrow] = rv.y;
            Xs[xq * 4 + 2][xrow] = rv.z;
            Xs[xq * 4 + 3][xrow] = rv.w;
        }
        // load W tile: 256 cols x 16 k (four float4 per thread, col = tid)
        {
            const float* wr = W_e + (size_t)tid * EE + k0;
            #pragma unroll
            for (int q = 0; q < 4; q++) {
                float4 wv = *(const float4*)(wr + q * 4);
                Ws[q * 4 + 0][tid] = wv.x;
                Ws[q * 4 + 1][tid] = wv.y;
                Ws[q * 4 + 2][tid] = wv.z;
                Ws[q * 4 + 3][tid] = wv.w;
            }
        }
        __syncthreads();

        #pragma unroll
        for (int kk = 0; kk < BK; kk++) {
            float4 a0 = *(const float4*)&Xs[kk][ty * 8];
            float4 a1 = *(const float4*)&Xs[kk][ty * 8 + 4];
            float4 b0 = *(const float4*)&Ws[kk][tx * 8];
            float4 b1 = *(const float4*)&Ws[kk][tx * 8 + 4];
            float av[8] = {a0.x, a0.y, a0.z, a0.w, a1.x, a1.y, a1.z, a1.w};
            float bv[8] = {b0.x, b0.y, b0.z, b0.w, b1.x, b1.y, b1.z, b1.w};
            #pragma unroll
            for (int i = 0; i < 8; i++)
                #pragma unroll
                for (int j = 0; j < 8; j++)
                    acc[i][j] += av[i] * bv[j];
        }
        __syncthreads();
    }

    // epilogue: + dproj, tanh, * v, reduce over a
    float vv[8];
    {
        float4 v0 = *(const float4*)(v + tx * 8);
        float4 v1 = *(const float4*)(v + tx * 8 + 4);
        vv[0] = v0.x; vv[1] = v0.y; vv[2] = v0.z; vv[3] = v0.w;
        vv[4] = v1.x; vv[5] = v1.y; vv[6] = v1.z; vv[7] = v1.w;
    }
    #pragma unroll
    for (int i = 0; i < 8; i++) {
        int n = ty * 8 + i;                         // row_local == n
        const float4* dp = (const float4*)&g_dproj[n * AA + tx * 8];
        float4 d0 = dp[0], d1 = dp[1];
        float dv[8] = {d0.x, d0.y, d0.z, d0.w, d1.x, d1.y, d1.z, d1.w};
        float s = 0.f;
        #pragma unroll
        for (int j = 0; j < 8; j++)
            s += tanhf(acc[i][j] + dv[j]) * vv[j];
        #pragma unroll
        for (int off = 16; off; off >>= 1)
            s += __shfl_xor_sync(0xffffffffu, s, off);
        if (tx == 0) g_scores[t * NN + n] = s;
    }
}

// ---------------------------------------------------------------------------
// Kernel 3: softmax over t (per column n). grid=64, block=256, 8 vals/thread.
// Writes alpha[t][n] into the output buffer.
// ---------------------------------------------------------------------------
__global__ void softmax_kernel(float* __restrict__ alpha) {
    int n = blockIdx.x, tid = threadIdx.x;
    int warp = tid >> 5, lane = tid & 31;
    __shared__ float red_max[8];
    __shared__ float red_sum[8];

    float vals[8];
    float lmax = -1e30f;
    #pragma unroll
    for (int i = 0; i < 8; i++) {
        vals[i] = g_scores[(i * 256 + tid) * NN + n];
        lmax = fmaxf(lmax, vals[i]);
    }
    #pragma unroll
    for (int off = 16; off; off >>= 1)
        lmax = fmaxf(lmax, __shfl_xor_sync(0xffffffffu, lmax, off));
    if (lane == 0) red_max[warp] = lmax;
    __syncthreads();
    float bmax = red_max[0];
    #pragma unroll
    for (int w = 1; w < 8; w++) bmax = fmaxf(bmax, red_max[w]);

    float lsum = 0.f;
    #pragma unroll
    for (int i = 0; i < 8; i++) {
        vals[i] = expf(vals[i] - bmax);
        lsum += vals[i];
    }
    #pragma unroll
    for (int off = 16; off; off >>= 1)
        lsum += __shfl_xor_sync(0xffffffffu, lsum, off);
    if (lane == 0) red_sum[warp] = lsum;
    __syncthreads();
    float bsum = 0.f;
    #pragma unroll
    for (int w = 0; w < 8; w++) bsum += red_sum[w];
    float inv = 1.f / bsum;

    #pragma unroll
    for (int i = 0; i < 8; i++)
        alpha[(i * 256 + tid) * NN + n] = vals[i] * inv;
}

// ---------------------------------------------------------------------------
// Kernel 4a: zero ctx region. 65536 floats.
// ---------------------------------------------------------------------------
__global__ void zero_ctx_kernel(float* __restrict__ ctx) {
    ctx[blockIdx.x * 256 + threadIdx.x] = 0.f;
}

// ---------------------------------------------------------------------------
// Kernel 4b: ctx[n][e] = sum_t alpha[t][n] * enc[t][n][e]
// grid = (8 e-chunks * 4 t-chunks, 64 n), block = 128 (one e per thread)
// ---------------------------------------------------------------------------
__global__ void ctx_kernel(const float* __restrict__ enc,
                           const float* __restrict__ alpha,
                           float* __restrict__ ctx) {
    int n = blockIdx.y;
    int echunk = blockIdx.x & 7;
    int tchunk = blockIdx.x >> 3;
    int e = echunk * 128 + threadIdx.x;
    int t0 = tchunk * 512;

    const float* base = enc + (size_t)n * EE + e;
    float acc = 0.f;
    #pragma unroll 4
    for (int t = t0; t < t0 + 512; t++) {
        float a = alpha[t * NN + n];              // uniform across block
        acc += a * base[(size_t)t * NN * EE];
    }
    atomicAdd(&ctx[n * EE + e], acc);
}

// ---------------------------------------------------------------------------
extern "C" void kernel_launch(void* const* d_in, const int* in_sizes, int n_in,
                              void* d_out, int out_size) {
    const float* enc_out = (const float*)d_in[0];  // [2048, 64, 1024]
    const float* dec_h   = (const float*)d_in[1];  // [64, 1024]
    const float* W_e     = (const float*)d_in[2];  // [256, 1024]
    const float* W_d     = (const float*)d_in[3];  // [256, 1024]
    const float* v       = (const float*)d_in[4];  // [1, 256]

    float* out   = (float*)d_out;
    float* ctx   = out;                 // [64, 1024]  -> 65536 floats
    float* alpha = out + NN * EE;       // [2048, 64]  -> 131072 floats

    dproj_kernel<<<NN, 256>>>(dec_h, W_d);
    score_kernel<<<TT, 256>>>(enc_out, W_e, v);
    softmax_kernel<<<NN, 256>>>(alpha);
    zero_ctx_kernel<<<(NN * EE) / 256, 256>>>(ctx);
    ctx_kernel<<<dim3(32, NN), 128>>>(enc_out, alpha, ctx);
}

// round 5
// speedup vs baseline: 3.2646x; 3.2646x over previous
#include <cuda_runtime.h>
#include <cuda_fp16.h>
#include <math.h>
#include <stdint.h>

#define TT 2048
#define NN 64
#define EE 1024
#define AA 256

// ---------------- device scratch (allocation-free rule) ----------------
__device__ float g_dproj[NN * AA];        // [n][a]
__device__ float g_scores[TT * NN];       // [t][n]
// W_e split into fp16 hi/lo, PRE-SWIZZLED per 64-k chunk:
// byte index = chunk*32768 + SWZ(row*128 + (k%64)*2)
__device__ unsigned char g_Wh[AA * EE * 2];
__device__ unsigned char g_Wl[AA * EE * 2];

#define SWZ(o) ((o) ^ ((((o) >> 3) & 0x70)))

// ---------------- PTX helpers (all plain sm_80/sm_90 features) ----------------
__device__ __forceinline__ uint32_t smem_u32(const void* p) {
    uint32_t a;
    asm("{ .reg .u64 t; cvta.to.shared.u64 t, %1; cvt.u32.u64 %0, t; }"
        : "=r"(a) : "l"(p));
    return a;
}
__device__ __forceinline__ void cp16(uint32_t dst, const void* src) {
    asm volatile("cp.async.cg.shared.global [%0], [%1], 16;"
                 :: "r"(dst), "l"(src) : "memory");
}
__device__ __forceinline__ void cp_commit() {
    asm volatile("cp.async.commit_group;" ::: "memory");
}
__device__ __forceinline__ void cp_wait0() {
    asm volatile("cp.async.wait_group 0;" ::: "memory");
}
__device__ __forceinline__ void ldmx4(uint32_t addr, uint32_t& r0, uint32_t& r1,
                                      uint32_t& r2, uint32_t& r3) {
    asm volatile("ldmatrix.sync.aligned.m8n8.x4.shared.b16 {%0,%1,%2,%3}, [%4];"
                 : "=r"(r0), "=r"(r1), "=r"(r2), "=r"(r3) : "r"(addr));
}
__device__ __forceinline__ void sts128(uint32_t addr, uint32_t a, uint32_t b,
                                       uint32_t c, uint32_t d) {
    asm volatile("st.shared.v4.b32 [%0], {%1,%2,%3,%4};"
                 :: "r"(addr), "r"(a), "r"(b), "r"(c), "r"(d) : "memory");
}
__device__ __forceinline__ void mma16816(float* c, const uint32_t* a,
                                         uint32_t b0, uint32_t b1) {
    asm volatile("mma.sync.aligned.m16n8k16.row.col.f32.f16.f16.f32 "
                 "{%0,%1,%2,%3}, {%4,%5,%6,%7}, {%8,%9}, {%0,%1,%2,%3};"
                 : "+f"(c[0]), "+f"(c[1]), "+f"(c[2]), "+f"(c[3])
                 : "r"(a[0]), "r"(a[1]), "r"(a[2]), "r"(a[3]), "r"(b0), "r"(b1));
}
__device__ __forceinline__ float tanh_fast(float x) {
    float y;
    asm("tanh.approx.f32 %0, %1;" : "=f"(y) : "f"(x));
    return y;
}

// ---------------------------------------------------------------------------
// Kernel 0: split W_e into fp16 hi/lo, pre-swizzled per 64-k chunk.
// ---------------------------------------------------------------------------
__global__ void wsplit_kernel(const float* __restrict__ W_e) {
    int row = blockIdx.x;
    int k4 = threadIdx.x * 4;
    float4 w = *(const float4*)(W_e + (size_t)row * EE + k4);
    int c = k4 >> 6, kl = k4 & 63;
    uint32_t off = (uint32_t)c * 32768u + SWZ((uint32_t)(row * 128 + kl * 2));

    __half h0 = __float2half_rn(w.x), h1 = __float2half_rn(w.y);
    __half h2 = __float2half_rn(w.z), h3 = __float2half_rn(w.w);
    __half l0 = __float2half_rn(w.x - __half2float(h0));
    __half l1 = __float2half_rn(w.y - __half2float(h1));
    __half l2 = __float2half_rn(w.z - __half2float(h2));
    __half l3 = __float2half_rn(w.w - __half2float(h3));
    __half2 hA = __halves2half2(h0, h1), hB = __halves2half2(h2, h3);
    __half2 lA = __halves2half2(l0, l1), lB = __halves2half2(l2, l3);

    *(uint32_t*)(g_Wh + off)     = *(uint32_t*)&hA;
    *(uint32_t*)(g_Wh + off + 4) = *(uint32_t*)&hB;
    *(uint32_t*)(g_Wl + off)     = *(uint32_t*)&lA;
    *(uint32_t*)(g_Wl + off + 4) = *(uint32_t*)&lB;
}

// ---------------------------------------------------------------------------
// Kernel 1: d_proj[n][a] = sum_k dec_h[n][k] * W_d[a][k]
// ---------------------------------------------------------------------------
__global__ void dproj_kernel(const float* __restrict__ dec_h,
                             const float* __restrict__ W_d) {
    __shared__ float dh[EE];
    int n = blockIdx.x;
    for (int k = threadIdx.x; k < EE; k += blockDim.x) dh[k] = dec_h[n * EE + k];
    __syncthreads();
    int warp = threadIdx.x >> 5, lane = threadIdx.x & 31;
    const float4* dh4 = (const float4*)dh;
    for (int a = warp; a < AA; a += 8) {
        const float4* w4 = (const float4*)(W_d + (size_t)a * EE);
        float acc = 0.f;
        #pragma unroll 4
        for (int k = lane; k < EE / 4; k += 32) {
            float4 w = w4[k], d = dh4[k];
            acc += w.x * d.x + w.y * d.y + w.z * d.z + w.w * d.w;
        }
        #pragma unroll
        for (int off = 16; off; off >>= 1)
            acc += __shfl_xor_sync(0xffffffffu, acc, off);
        if (lane == 0) g_dproj[n * AA + a] = acc;
    }
}

__global__ void dummy_kernel() {}

// ---------------------------------------------------------------------------
// Kernel 2: fused score via mma.sync (m16n8k16 f16), 2-pass W split.
//   CTA tile: BM=128 rows, BN=256 cols, BK=64. 256 threads, 8 warps (2m x 4n),
//   warp tile 64x64. X fp32->fp16 in-register; W via cp.async (prepacked).
//   Epilogue: score[row] = sum_a tanh(C + dproj[n][a]) * v[a]  (tanh.approx)
// ---------------------------------------------------------------------------
#define XS_OFF(b)    ((b) * 16384)
#define WS_OFF(b, s) (32768 + (b) * 65536 + (s) * 32768)
#define SCORE_SMEM   163840
#define DPS 260  // padded dproj smem stride (floats)

extern "C" __global__ void __launch_bounds__(256, 1)
score_kernel(const float* __restrict__ enc, const float* __restrict__ v) {
    extern __shared__ char dsm[];
    __shared__ float red[128][4];

    const int tid = threadIdx.x;
    const int lane = tid & 31, wid = tid >> 5;
    const int wm = wid & 1, wn = wid >> 1;
    const uint32_t smem = smem_u32(dsm);

    // ---- X load/store mapping: row = tid>>1, half = tid&1 (32 k each) ----
    const int xrow = tid >> 1, xhalf = tid & 1;
    const float* xg = enc + ((size_t)blockIdx.x * 128 + xrow) * EE + xhalf * 32;
    uint32_t xsts[4];
    #pragma unroll
    for (int u = 0; u < 4; u++)
        xsts[u] = SWZ((uint32_t)(xrow * 128 + xhalf * 64 + u * 16));

    // ---- ldmatrix per-thread geometry ----
    const int g = lane >> 3, lr8 = lane & 7;
    const int arow = wm * 64 + lr8 + (g & 1) * 8;   // + mi*16
    const int brow = wn * 64 + lr8 + (g & 1) * 8;   // + nb*16
    const int kgrp = (g >> 1) * 16;                 // + ks*32 (bytes)

    float acc[4][8][4];
    #pragma unroll
    for (int mi = 0; mi < 4; mi++)
        #pragma unroll
        for (int nt = 0; nt < 8; nt++)
            #pragma unroll
            for (int q = 0; q < 4; q++) acc[mi][nt][q] = 0.f;

    // ---- prologue: X chunk 0 -> smem buf 0; W chunk 0 via cp.async ----
    float4 pa[8];
    {
        const float4* p = (const float4*)xg;
        #pragma unroll
        for (int u = 0; u < 8; u++) pa[u] = __ldg(p + u);
        #pragma unroll
        for (int u4 = 0; u4 < 4; u4++) {
            float4 a0 = pa[u4 * 2], a1 = pa[u4 * 2 + 1];
            __half2 q0 = __floats2half2_rn(a0.x, a0.y);
            __half2 q1 = __floats2half2_rn(a0.z, a0.w);
            __half2 q2 = __floats2half2_rn(a1.x, a1.y);
            __half2 q3 = __floats2half2_rn(a1.z, a1.w);
            sts128(smem + XS_OFF(0) + xsts[u4],
                   *(uint32_t*)&q0, *(uint32_t*)&q1, *(uint32_t*)&q2, *(uint32_t*)&q3);
        }
        #pragma unroll
        for (int s = 0; s < 2; s++) {
            const unsigned char* src = (s ? g_Wl : g_Wh) + tid * 16;
            uint32_t dst = smem + WS_OFF(0, s) + tid * 16;
            #pragma unroll
            for (int r = 0; r < 8; r++)
                cp16(dst + r * 4096, src + r * 4096);
        }
        cp_commit();
    }

    for (int c = 0; c < 16; c++) {
        const int b = c & 1;
        // start LDG for next X while waiting on this chunk's W
        if (c < 15) {
            const float4* p = (const float4*)(xg + (c + 1) * 64);
            #pragma unroll
            for (int u = 0; u < 8; u++) pa[u] = __ldg(p + u);
        }
        cp_wait0();
        __syncthreads();   // XS[b], WS[b] visible; b^1 buffers free

        if (c < 15) {
            #pragma unroll
            for (int u4 = 0; u4 < 4; u4++) {
                float4 a0 = pa[u4 * 2], a1 = pa[u4 * 2 + 1];
                __half2 q0 = __floats2half2_rn(a0.x, a0.y);
                __half2 q1 = __floats2half2_rn(a0.z, a0.w);
                __half2 q2 = __floats2half2_rn(a1.x, a1.y);
                __half2 q3 = __floats2half2_rn(a1.z, a1.w);
                sts128(smem + XS_OFF(b ^ 1) + xsts[u4],
                       *(uint32_t*)&q0, *(uint32_t*)&q1, *(uint32_t*)&q2, *(uint32_t*)&q3);
            }
            #pragma unroll
            for (int s = 0; s < 2; s++) {
                const unsigned char* src =
                    (s ? g_Wl : g_Wh) + (size_t)(c + 1) * 32768 + tid * 16;
                uint32_t dst = smem + WS_OFF(b ^ 1, s) + tid * 16;
                #pragma unroll
                for (int r = 0; r < 8; r++)
                    cp16(dst + r * 4096, src + r * 4096);
            }
            cp_commit();
        }

        // ---- MMA on buffer b: 4 k-steps x 2 splits x (4m x 8n) ----
        #pragma unroll
        for (int ks = 0; ks < 4; ks++) {
            uint32_t afr[4][4];
            #pragma unroll
            for (int mi = 0; mi < 4; mi++) {
                uint32_t ad = smem + XS_OFF(b) +
                              SWZ((uint32_t)((arow + mi * 16) * 128 + kgrp + ks * 32));
                ldmx4(ad, afr[mi][0], afr[mi][1], afr[mi][2], afr[mi][3]);
            }
            #pragma unroll
            for (int s = 0; s < 2; s++) {
                uint32_t bfr[4][4];
                #pragma unroll
                for (int nb = 0; nb < 4; nb++) {
                    uint32_t bd = smem + WS_OFF(b, s) +
                                  SWZ((uint32_t)((brow + nb * 16) * 128 + kgrp + ks * 32));
                    ldmx4(bd, bfr[nb][0], bfr[nb][1], bfr[nb][2], bfr[nb][3]);
                }
                #pragma unroll
                for (int mi = 0; mi < 4; mi++)
                    #pragma unroll
                    for (int nt = 0; nt < 8; nt++) {
                        int nb = nt >> 1, j = nt & 1;
                        mma16816(acc[mi][nt], afr[mi], bfr[nb][j], bfr[nb][2 + j]);
                    }
            }
        }
    }

    // ---- epilogue ----
    __syncthreads();
    // stage dproj [64][256] into smem with padded stride (reuses W area)
    float* dps = (float*)(dsm + 32768);
    for (int i = tid; i < NN * AA; i += 256) {
        int n = i >> 8, a = i & 255;
        dps[n * DPS + a] = g_dproj[i];
    }
    __syncthreads();

    float2 vv[8];
    #pragma unroll
    for (int nt = 0; nt < 8; nt++)
        vv[nt] = *(const float2*)(v + wn * 64 + nt * 8 + 2 * (lane & 3));

    #pragma unroll
    for (int mi = 0; mi < 4; mi++) {
        #pragma unroll
        for (int half = 0; half < 2; half++) {
            int n = mi * 16 + (lane >> 2) + half * 8;   // n index (row & 63)
            float partial = 0.f;
            #pragma unroll
            for (int nt = 0; nt < 8; nt++) {
                int col = wn * 64 + nt * 8 + 2 * (lane & 3);
                float2 dp = *(const float2*)(dps + n * DPS + col);
                float x0 = acc[mi][nt][half * 2 + 0] + dp.x;
                float x1 = acc[mi][nt][half * 2 + 1] + dp.y;
                partial = fmaf(tanh_fast(x0), vv[nt].x, partial);
                partial = fmaf(tanh_fast(x1), vv[nt].y, partial);
            }
            partial += __shfl_xor_sync(0xffffffffu, partial, 1);
            partial += __shfl_xor_sync(0xffffffffu, partial, 2);
            if ((lane & 3) == 0) {
                int lr = wm * 64 + n;
                red[lr][wn] = partial;
            }
        }
    }
    __syncthreads();
    if (tid < 128) {
        float s = red[tid][0] + red[tid][1] + red[tid][2] + red[tid][3];
        int t = blockIdx.x * 2 + (tid >> 6), n = tid & 63;
        g_scores[t * NN + n] = s;
    }
}

// ---------------------------------------------------------------------------
// Kernel 3: softmax over t per column n
// ---------------------------------------------------------------------------
__global__ void softmax_kernel(float* __restrict__ alpha) {
    int n = blockIdx.x, tid = threadIdx.x;
    int warp = tid >> 5, lane = tid & 31;
    __shared__ float red_max[8];
    __shared__ float red_sum[8];

    float vals[8];
    float lmax = -1e30f;
    #pragma unroll
    for (int i = 0; i < 8; i++) {
        vals[i] = g_scores[(i * 256 + tid) * NN + n];
        lmax = fmaxf(lmax, vals[i]);
    }
    #pragma unroll
    for (int off = 16; off; off >>= 1)
        lmax = fmaxf(lmax, __shfl_xor_sync(0xffffffffu, lmax, off));
    if (lane == 0) red_max[warp] = lmax;
    __syncthreads();
    float bmax = red_max[0];
    #pragma unroll
    for (int w = 1; w < 8; w++) bmax = fmaxf(bmax, red_max[w]);

    float lsum = 0.f;
    #pragma unroll
    for (int i = 0; i < 8; i++) {
        vals[i] = expf(vals[i] - bmax);
        lsum += vals[i];
    }
    #pragma unroll
    for (int off = 16; off; off >>= 1)
        lsum += __shfl_xor_sync(0xffffffffu, lsum, off);
    if (lane == 0) red_sum[warp] = lsum;
    __syncthreads();
    float bsum = 0.f;
    #pragma unroll
    for (int w = 0; w < 8; w++) bsum += red_sum[w];
    float inv = 1.f / bsum;

    #pragma unroll
    for (int i = 0; i < 8; i++)
        alpha[(i * 256 + tid) * NN + n] = vals[i] * inv;
}

// ---------------------------------------------------------------------------
__global__ void zero_ctx_kernel(float* __restrict__ ctx) {
    ctx[blockIdx.x * 256 + threadIdx.x] = 0.f;
}

__global__ void ctx_kernel(const float* __restrict__ enc,
                           const float* __restrict__ alpha,
                           float* __restrict__ ctx) {
    int n = blockIdx.y;
    int echunk = blockIdx.x & 7;
    int tchunk = blockIdx.x >> 3;
    int e = echunk * 128 + threadIdx.x;
    int t0 = tchunk * 512;

    const float* base = enc + (size_t)n * EE + e;
    float acc = 0.f;
    #pragma unroll 4
    for (int t = t0; t < t0 + 512; t++) {
        float a = alpha[t * NN + n];
        acc += a * base[(size_t)t * NN * EE];
    }
    atomicAdd(&ctx[n * EE + e], acc);
}

// ---------------------------------------------------------------------------
extern "C" void kernel_launch(void* const* d_in, const int* in_sizes, int n_in,
                              void* d_out, int out_size) {
    const float* enc_out = (const float*)d_in[0];  // [2048, 64, 1024]
    const float* dec_h   = (const float*)d_in[1];  // [64, 1024]
    const float* W_e     = (const float*)d_in[2];  // [256, 1024]
    const float* W_d     = (const float*)d_in[3];  // [256, 1024]
    const float* v       = (const float*)d_in[4];  // [1, 256]

    float* out   = (float*)d_out;
    float* ctx   = out;                 // [64, 1024]
    float* alpha = out + NN * EE;       // [2048, 64]

    cudaFuncSetAttribute(score_kernel,
                         cudaFuncAttributeMaxDynamicSharedMemorySize, SCORE_SMEM);

    wsplit_kernel<<<AA, 256>>>(W_e);                        // launch 0
    dproj_kernel<<<NN, 256>>>(dec_h, W_d);                  // launch 1
    dummy_kernel<<<1, 32>>>();                              // launch 2 (ncu pad)
    score_kernel<<<TT * NN / 128, 256, SCORE_SMEM>>>(enc_out, v);  // launch 3
    softmax_kernel<<<NN, 256>>>(alpha);                     // launch 4
    zero_ctx_kernel<<<(NN * EE) / 256, 256>>>(ctx);         // launch 5
    ctx_kernel<<<dim3(32, NN), 128>>>(enc_out, alpha, ctx); // launch 6
}